// round 16
// baseline (speedup 1.0000x reference)
#include <cuda_runtime.h>
#include <cuda_fp16.h>
#include <cstdint>

#define NT_TOK 4096
#define DIM    2048
#define FDIM   4096
#define TWOF   8192
#define NEXP   8

// ---------------- static device scratch ----------------
__device__ int    g_cnt[9];        // zeroed at end of gather for next replay
__device__ int    g_cnt2[9];       // stable copy for gemm kernels
__device__ int    g_off[9];
__device__ int    g_list[NEXP * NT_TOK];
__device__ float  g_gate[NEXP * NT_TOK];
__device__ __half g_X[2 * NT_TOK * (size_t)DIM];   // gathered gated input (fp16)
__device__ __half g_H[2 * NT_TOK * (size_t)FDIM];  // silu(g)*u (fp16)

// ---------------- helpers (arch-neutral) ----------------
__device__ __forceinline__ uint32_t h2u(float a, float b) {
    __half2 h = __floats2half2_rn(a, b);
    return *reinterpret_cast<uint32_t*>(&h);
}
__device__ __forceinline__ uint32_t smem_u32(const void* p) {
    uint32_t a;
    asm("{ .reg .u64 t; cvta.to.shared.u64 t, %1; cvt.u32.u64 %0, t; }" : "=r"(a) : "l"(p));
    return a;
}
#define SW128(o) ((o) ^ (((o) >> 3) & 0x70))

#if defined(__CUDA_ARCH__) && defined(__CUDA_ARCH_FEAT_SM103_ALL)
#define HAS_TCGEN05 1
#else
#define HAS_TCGEN05 0
#endif

#if HAS_TCGEN05
__device__ __forceinline__ uint32_t elect_one() {
    uint32_t p;
    asm volatile("{\n\t.reg .pred p;\n\telect.sync _|p, 0xFFFFFFFF;\n\t"
                 "selp.b32 %0, 1, 0, p;\n\t}" : "=r"(p));
    return p;
}
static __device__ __forceinline__ uint64_t make_desc_sw128(uint32_t addr) {
    const uint64_t base =
        (uint64_t(2) << 61) | (uint64_t(1) << 46) | (uint64_t(64) << 32) | (uint64_t(1) << 16);
    return base | ((uint64_t)(addr >> 4) & 0x3FFF);
}
// cg2 f16: dtype=F32(1)<<4 | atype=FP16(0)<<7 | btype=FP16(0)<<10 | (N/8)<<17 | (M/16)<<24
#define IDESC_F16_CG2 ((1u<<4)|((256u/8)<<17)|((256u/16)<<24))

__device__ __forceinline__ void mma_f16_ss_cg2(uint32_t d, uint64_t da, uint64_t db,
                                               uint32_t idesc, uint32_t en) {
    asm volatile(
        "{\n\t.reg .pred p;\n\tsetp.ne.u32 p, %4, 0;\n\t"
        "tcgen05.mma.cta_group::2.kind::f16 [%0], %1, %2, %3, "
        "{%5, %5, %5, %5, %5, %5, %5, %5}, p;\n\t}"
        :: "r"(d), "l"(da), "l"(db), "r"(idesc), "r"(en), "r"(0u) : "memory");
}

#define TC_ALLOC_CG2(sm, n)   asm volatile("tcgen05.alloc.cta_group::2.sync.aligned.shared::cta.b32 [%0], %1;" :: "r"(sm), "r"(n) : "memory")
#define TC_DEALLOC_CG2(tb, n) asm volatile("tcgen05.dealloc.cta_group::2.sync.aligned.b32 %0, %1;" :: "r"(tb), "r"(n))
#define TC_RELINQ_CG2()       asm volatile("tcgen05.relinquish_alloc_permit.cta_group::2.sync.aligned;")
#define TC_COMMIT_MC_CG2(mb, mask) \
    asm volatile("tcgen05.commit.cta_group::2.mbarrier::arrive::one.shared::cluster.multicast::cluster.b64 [%0], %1;" \
                 :: "r"(mb), "h"((uint16_t)(mask)) : "memory")
#define TC_FENCE_AFTER()  asm volatile("tcgen05.fence::after_thread_sync;" ::: "memory")
#define TC_WAIT_LD()      asm volatile("tcgen05.wait::ld.sync.aligned;" ::: "memory")
#define FENCE_ASYNC()     asm volatile("fence.proxy.async.shared::cta;" ::: "memory")
#define MBAR_INIT(mb, c)  asm volatile("mbarrier.init.shared.b64 [%0], %1;" :: "r"(mb), "r"(c) : "memory")
#define MBAR_INVAL(mb)    asm volatile("mbarrier.inval.shared.b64 [%0];" :: "r"(mb) : "memory")
#define MBAR_ARRIVE_LEADER(mb)                                                       \
    asm volatile("{\n\t.reg .b32 la;\n\tand.b32 la, %0, 0xFEFFFFFF;\n\t"             \
                 "mbarrier.arrive.shared::cluster.b64 _, [la];\n\t}"                 \
                 :: "r"(mb) : "memory")
#define CLUSTER_SYNC() do {                                                          \
    asm volatile("barrier.cluster.arrive.aligned;" ::: "memory");                    \
    asm volatile("barrier.cluster.wait.aligned;" ::: "memory");                      \
} while (0)

#define MBAR_WAIT(mb, ph) do {                                                       \
    uint32_t _m = (mb); uint32_t _p = (ph); uint32_t _d;                             \
    asm volatile("{\n\t.reg .pred p;\n\t"                                            \
        "mbarrier.try_wait.parity.acquire.cta.shared::cta.b64 p, [%1], %2;\n\t"      \
        "selp.b32 %0, 1, 0, p;\n\t}" : "=r"(_d) : "r"(_m), "r"(_p) : "memory");      \
    if (!_d) {                                                                       \
        asm volatile("{\n\t.reg .pred P1;\n\tWL_%=:\n\t"                             \
            "mbarrier.try_wait.parity.acquire.cta.shared::cta.b64 P1, [%0], %1, 0x989680;\n\t" \
            "@P1 bra.uni WD_%=;\n\tbra.uni WL_%=;\n\tWD_%=:\n\t}"                    \
            :: "r"(_m), "r"(_p) : "memory");                                         \
    }                                                                                \
} while (0)

#define TC_LD_X32(r, addr)                                                           \
    asm volatile("tcgen05.ld.sync.aligned.32x32b.x32.b32 "                           \
        "{%0,%1,%2,%3,%4,%5,%6,%7,%8,%9,%10,%11,%12,%13,%14,%15,"                    \
        "%16,%17,%18,%19,%20,%21,%22,%23,%24,%25,%26,%27,%28,%29,%30,%31}, [%32];"   \
        : "=r"((r)[0]),"=r"((r)[1]),"=r"((r)[2]),"=r"((r)[3]),                       \
          "=r"((r)[4]),"=r"((r)[5]),"=r"((r)[6]),"=r"((r)[7]),                       \
          "=r"((r)[8]),"=r"((r)[9]),"=r"((r)[10]),"=r"((r)[11]),                     \
          "=r"((r)[12]),"=r"((r)[13]),"=r"((r)[14]),"=r"((r)[15]),                   \
          "=r"((r)[16]),"=r"((r)[17]),"=r"((r)[18]),"=r"((r)[19]),                   \
          "=r"((r)[20]),"=r"((r)[21]),"=r"((r)[22]),"=r"((r)[23]),                   \
          "=r"((r)[24]),"=r"((r)[25]),"=r"((r)[26]),"=r"((r)[27]),                   \
          "=r"((r)[28]),"=r"((r)[29]),"=r"((r)[30]),"=r"((r)[31])                    \
        : "r"(addr))

#define STS128(addr, a, b, c, d)                                                     \
    asm volatile("st.shared.v4.b32 [%0], {%1, %2, %3, %4};"                          \
                 :: "r"(addr), "r"(a), "r"(b), "r"(c), "r"(d) : "memory")
#endif  // HAS_TCGEN05

// K_tile=128 halves. stage = A(32KB: 2 katom-cols of 16KB) + B(64KB: 2 of 32KB)
#define STAGE_BYTES 98304
#define NSTAGE 2
#define SMEM_BYTES (2048 + NSTAGE * STAGE_BYTES)
#define NTHREADS 544
#define FULL_ARRIVALS 32

// ---------------- router ----------------
__global__ __launch_bounds__(256) void router_kernel(
    const float* __restrict__ x, const float* __restrict__ rw)
{
    int t = blockIdx.x * 8 + (threadIdx.x >> 5);
    int lane = threadIdx.x & 31;
    const float* xr = x + (size_t)t * DIM;
    float p[8];
#pragma unroll
    for (int e = 0; e < 8; e++) p[e] = 0.f;
    for (int k = lane; k < DIM; k += 32) {
        float xv = xr[k];
#pragma unroll
        for (int e = 0; e < 8; e++) p[e] += xv * rw[e * DIM + k];
    }
#pragma unroll
    for (int e = 0; e < 8; e++)
#pragma unroll
        for (int o = 16; o > 0; o >>= 1) p[e] += __shfl_xor_sync(~0u, p[e], o);
    if (lane == 0) {
        float best = p[0]; int bi = 0;
#pragma unroll
        for (int e = 1; e < 8; e++) if (p[e] > best) { best = p[e]; bi = e; }
        float gate = 1.0f / (1.0f + expf(-best));
        int pos = atomicAdd(&g_cnt[bi], 1);
        g_list[bi * NT_TOK + pos] = t;
        g_gate[bi * NT_TOK + pos] = gate;
    }
}

__global__ void finalize_kernel() {
    int o = 0;
    for (int e = 0; e < 8; e++) { g_off[e] = o; g_cnt2[e] = g_cnt[e]; o += g_cnt[e]; }
    g_off[8] = NT_TOK; g_cnt2[8] = NT_TOK;
}

// ---------------- gather: g_X[slot] = fp16(gate * x[tok]); re-zero g_cnt ----
__global__ __launch_bounds__(256) void gather_kernel(const float* __restrict__ x)
{
    int row = blockIdx.x;
    int tok; float gate;
    if (row < NT_TOK) {
        int e = 0;
#pragma unroll
        for (int i = 1; i < 8; i++) if (row >= g_off[i]) e = i;
        int idx = row - g_off[e];
        tok  = g_list[e * NT_TOK + idx];
        gate = g_gate[e * NT_TOK + idx];
    } else { tok = row - NT_TOK; gate = 1.f; }
    const float4* src = (const float4*)(x + (size_t)tok * DIM);
    __half2* dst = (__half2*)(g_X + (size_t)row * DIM);
    for (int j = threadIdx.x; j < DIM / 4; j += 256) {
        float4 v = src[j];
        dst[j * 2]     = __floats2half2_rn(v.x * gate, v.y * gate);
        dst[j * 2 + 1] = __floats2half2_rn(v.z * gate, v.w * gate);
    }
    if (blockIdx.x == 0 && threadIdx.x < 9) g_cnt[threadIdx.x] = 0;
}

// ================= GEMM1 (cg2 pair tile M=256 x N=512, fp16, K_tile=128) =====
// grid: (2*NT_TOK/256, FDIM/256, 9). cluster (2,1,1), block 544.
__global__ __launch_bounds__(NTHREADS, 1) __cluster_dims__(2, 1, 1)
void gemm1_tc(const float* __restrict__ wgu, const float* __restrict__ sgu)
{
    const int g   = blockIdx.z;
    const int cnt = (g < NEXP) ? g_cnt2[g] : NT_TOK;
    const int m0  = (blockIdx.x >> 1) * 256;
    if (m0 >= cnt) return;
    const int rank = blockIdx.x & 1;
    const int hb  = blockIdx.y;
    const float* Bsrc = (g < NEXP) ? (wgu + (size_t)g * DIM * TWOF) : sgu;
    const int rowbase = (g < NEXP) ? g_off[g] : NT_TOK;

#if HAS_TCGEN05
    extern __shared__ char smraw[];
    uint32_t sb = (smem_u32(smraw) + 1023u) & ~1023u;
    const uint32_t TP  = sb + 64;
    const uint32_t BUF = sb + 1024;

    const int tid = threadIdx.x, wid = tid >> 5, lane = tid & 31;

    if (wid == 0) { TC_ALLOC_CG2(TP, 512); TC_RELINQ_CG2(); }
    if (tid == 0) {
#pragma unroll
        for (int s = 0; s < 2; s++) { MBAR_INIT(sb + s * 8, FULL_ARRIVALS); MBAR_INIT(sb + 32 + s * 8, 1); }
    }
    __syncthreads();
    CLUSTER_SYNC();
    uint32_t tb;
    asm volatile("ld.shared.b32 %0, [%1];" : "=r"(tb) : "r"(TP));

    const int T = DIM / 128;

    if (tid < 512) {
        // A: 128 rows x 128 k halves; thread: sub=tid&7 (16B=8 halves), rows tid>>3, +64
        const int asub = tid & 7;
        const int ar0  = tid >> 3;        // 0..63
        const __half* abase = g_X + (size_t)(rowbase + m0 + rank * 128) * DIM;
        uint32_t ao[2];
#pragma unroll
        for (int j = 0; j < 2; j++)
            ao[j] = SW128((uint32_t)((ar0 + 64 * j) * 128 + asub * 16));

        // B: 256 n-rows x 128 k halves; thread: sub=tid&7, n-rows tid>>3 + 64j
        int gcols[4]; uint32_t bo[4];
#pragma unroll
        for (int j = 0; j < 4; j++) {
            int nr = (tid >> 3) + 64 * j;
            int atom = nr >> 7, within = nr & 127;
            gcols[j] = (atom == 0) ? (hb * 256 + rank * 128 + within)
                                   : (FDIM + hb * 256 + rank * 128 + within);
            bo[j] = SW128((uint32_t)(nr * 128 + asub * 16));
        }

        int phD[2] = {0, 0};
        for (int t = 0; t < T; t++) {
            const int s = t & 1;
            const uint32_t Ab = BUF + (uint32_t)s * STAGE_BYTES;
            const uint32_t Bb = Ab + 32768;
            // issue loads: A (4x16B) and B col0 (32 scalars)
            uint4 rA[2][2];
            float f0[4][8];
#pragma unroll
            for (int col = 0; col < 2; col++)
#pragma unroll
                for (int j = 0; j < 2; j++)
                    rA[col][j] = *(const uint4*)(abase + (size_t)(ar0 + 64 * j) * DIM
                                                 + t * 128 + col * 64 + asub * 8);
            {
                const size_t k0 = (size_t)(t * 128 + asub * 8);
#pragma unroll
                for (int j = 0; j < 4; j++)
#pragma unroll
                    for (int d = 0; d < 8; d++)
                        f0[j][d] = Bsrc[(k0 + d) * TWOF + gcols[j]];
            }
            if (t >= 2) { MBAR_WAIT(sb + 32 + s * 8, phD[s]); phD[s] ^= 1; }
#pragma unroll
            for (int col = 0; col < 2; col++)
#pragma unroll
                for (int j = 0; j < 2; j++)
                    STS128(Ab + col * 16384 + ao[j],
                           rA[col][j].x, rA[col][j].y, rA[col][j].z, rA[col][j].w);
#pragma unroll
            for (int j = 0; j < 4; j++)
                STS128(Bb + bo[j], h2u(f0[j][0], f0[j][1]), h2u(f0[j][2], f0[j][3]),
                                   h2u(f0[j][4], f0[j][5]), h2u(f0[j][6], f0[j][7]));
            // B col1 (k +64)
            {
                const size_t k1 = (size_t)(t * 128 + 64 + asub * 8);
                float f1[4][8];
#pragma unroll
                for (int j = 0; j < 4; j++)
#pragma unroll
                    for (int d = 0; d < 8; d++)
                        f1[j][d] = Bsrc[(k1 + d) * TWOF + gcols[j]];
#pragma unroll
                for (int j = 0; j < 4; j++)
                    STS128(Bb + 32768 + bo[j], h2u(f1[j][0], f1[j][1]), h2u(f1[j][2], f1[j][3]),
                                               h2u(f1[j][4], f1[j][5]), h2u(f1[j][6], f1[j][7]));
            }
            FENCE_ASYNC();
            __syncwarp();
            if (lane == 0) MBAR_ARRIVE_LEADER(sb + s * 8);
        }
        { const int sf = (T - 1) & 1; MBAR_WAIT(sb + 32 + sf * 8, phD[sf]); }
    } else if (rank == 0) {
        if (elect_one()) {
            int phF[2] = {0, 0};
            for (int t = 0; t < T; t++) {
                const int s = t & 1;
                const uint32_t Ab = BUF + (uint32_t)s * STAGE_BYTES;
                const uint32_t Bb = Ab + 32768;
                MBAR_WAIT(sb + s * 8, phF[s]); phF[s] ^= 1;
                uint64_t dA = make_desc_sw128(Ab);
                uint64_t dB = make_desc_sw128(Bb);
#pragma unroll
                for (int c = 0; c < 8; c++) {   // 8 K16 chunks: katom=c>>2, sub=c&3
                    uint64_t ao2 = (uint64_t)((c >> 2) * 1024 + (c & 3) * 2);
                    uint64_t bo2 = (uint64_t)((c >> 2) * 2048 + (c & 3) * 2);
                    uint32_t en = (t > 0 || c > 0) ? 1u : 0u;
                    mma_f16_ss_cg2(tb,       dA + ao2, dB + bo2,        IDESC_F16_CG2, en);
                    mma_f16_ss_cg2(tb + 256, dA + ao2, dB + bo2 + 1024, IDESC_F16_CG2, en);
                }
                TC_COMMIT_MC_CG2(sb + 32 + s * 8, 0x3);
            }
        }
    }
    TC_FENCE_AFTER();

    // ---- epilogue: my 128 rows x 512 cols (gate atom0 | up atom1) -> g_H (fp16) ----
    if (wid < 16) {
        const int rloc = (wid & 3) * 32 + lane;
        const int row  = m0 + rank * 128 + rloc;
        const bool ok  = row < cnt;
        const int cq   = wid >> 2;
        const size_t hbase = (size_t)(rowbase + row) * FDIM + hb * 256 + cq * 64;
#pragma unroll
        for (int c = 0; c < 2; c++) {
            uint32_t gr[32], ur[32];
            uint32_t col = (uint32_t)(cq * 64 + c * 32);
            TC_LD_X32(gr, tb + col);
            TC_LD_X32(ur, tb + 256 + col);
            TC_WAIT_LD();
            if (ok) {
                uint32_t hp[16];
#pragma unroll
                for (int r = 0; r < 16; r++) {
                    float gv0 = __uint_as_float(gr[2*r]),   uv0 = __uint_as_float(ur[2*r]);
                    float gv1 = __uint_as_float(gr[2*r+1]), uv1 = __uint_as_float(ur[2*r+1]);
                    hp[r] = h2u(gv0 / (1.f + expf(-gv0)) * uv0,
                                gv1 / (1.f + expf(-gv1)) * uv1);
                }
#pragma unroll
                for (int q = 0; q < 4; q++)
                    *(uint4*)&g_H[hbase + c * 32 + q * 8] =
                        make_uint4(hp[q*4], hp[q*4+1], hp[q*4+2], hp[q*4+3]);
            }
        }
    }
    __syncthreads();
    if (tid == 0) {
#pragma unroll
        for (int s = 0; s < 2; s++) { MBAR_INVAL(sb + s * 8); MBAR_INVAL(sb + 32 + s * 8); }
    }
    __syncthreads();
    if (wid == 0) { TC_DEALLOC_CG2(tb, 512); }
    CLUSTER_SYNC();
#else
    // portable fallback
    for (int idx = threadIdx.x; idx < 128 * 256; idx += NTHREADS) {
        int r = idx >> 8, cc = idx & 255;
        int row = m0 + rank * 128 + r;
        if (row >= cnt) continue;
        const __half* arow = g_X + (size_t)(rowbase + row) * DIM;
        int col = hb * 256 + cc;
        float sg = 0.f, su = 0.f;
        for (int k = 0; k < DIM; k++) {
            float a = __half2float(arow[k]);
            sg += a * __half2float(__float2half_rn(Bsrc[(size_t)k * TWOF + col]));
            su += a * __half2float(__float2half_rn(Bsrc[(size_t)k * TWOF + FDIM + col]));
        }
        g_H[(size_t)(rowbase + row) * FDIM + col] =
            __float2half_rn(sg / (1.f + expf(-sg)) * su);
    }
#endif
}

// ================= GEMM2 (cg2 pair tile M=256 x N=512, fp16, K_tile=128) =====
// grid: (2*NT_TOK/256, DIM/512, nz). cluster (2,1,1), block 544.
__global__ __launch_bounds__(NTHREADS, 1) __cluster_dims__(2, 1, 1)
void gemm2_tc(const float* __restrict__ wdn, const float* __restrict__ sdn,
              float* __restrict__ out, int gstart, int accumulate)
{
    const int g   = gstart + blockIdx.z;
    const int cnt = (g < NEXP) ? g_cnt2[g] : NT_TOK;
    const int m0  = (blockIdx.x >> 1) * 256;
    if (m0 >= cnt) return;
    const int rank = blockIdx.x & 1;
    const int n0  = blockIdx.y * 512;
    const float* Bsrc = (g < NEXP) ? (wdn + (size_t)g * FDIM * DIM) : sdn;
    const int rowbase = (g < NEXP) ? g_off[g] : NT_TOK;

#if HAS_TCGEN05
    extern __shared__ char smraw[];
    uint32_t sb = (smem_u32(smraw) + 1023u) & ~1023u;
    const uint32_t TP  = sb + 64;
    const uint32_t BUF = sb + 1024;

    const int tid = threadIdx.x, wid = tid >> 5, lane = tid & 31;

    if (wid == 0) { TC_ALLOC_CG2(TP, 512); TC_RELINQ_CG2(); }
    if (tid == 0) {
#pragma unroll
        for (int s = 0; s < 2; s++) { MBAR_INIT(sb + s * 8, FULL_ARRIVALS); MBAR_INIT(sb + 32 + s * 8, 1); }
    }
    __syncthreads();
    CLUSTER_SYNC();
    uint32_t tb;
    asm volatile("ld.shared.b32 %0, [%1];" : "=r"(tb) : "r"(TP));

    const int T = FDIM / 128;

    if (tid < 512) {
        const int asub = tid & 7;
        const int ar0  = tid >> 3;
        const __half* abase = g_H + (size_t)(rowbase + m0 + rank * 128) * FDIM;
        uint32_t ao[2];
#pragma unroll
        for (int j = 0; j < 2; j++)
            ao[j] = SW128((uint32_t)((ar0 + 64 * j) * 128 + asub * 16));

        int gcols[4]; uint32_t bo[4];
#pragma unroll
        for (int j = 0; j < 4; j++) {
            int nr = (tid >> 3) + 64 * j;
            int atom = nr >> 7, within = nr & 127;
            gcols[j] = n0 + atom * 256 + rank * 128 + within;
            bo[j] = SW128((uint32_t)(nr * 128 + asub * 16));
        }

        int phD[2] = {0, 0};
        for (int t = 0; t < T; t++) {
            const int s = t & 1;
            const uint32_t Ab = BUF + (uint32_t)s * STAGE_BYTES;
            const uint32_t Bb = Ab + 32768;
            uint4 rA[2][2];
            float f0[4][8];
#pragma unroll
            for (int col = 0; col < 2; col++)
#pragma unroll
                for (int j = 0; j < 2; j++)
                    rA[col][j] = *(const uint4*)(abase + (size_t)(ar0 + 64 * j) * FDIM
                                                 + t * 128 + col * 64 + asub * 8);
            {
                const size_t k0 = (size_t)(t * 128 + asub * 8);
#pragma unroll
                for (int j = 0; j < 4; j++)
#pragma unroll
                    for (int d = 0; d < 8; d++)
                        f0[j][d] = Bsrc[(k0 + d) * DIM + gcols[j]];
            }
            if (t >= 2) { MBAR_WAIT(sb + 32 + s * 8, phD[s]); phD[s] ^= 1; }
#pragma unroll
            for (int col = 0; col < 2; col++)
#pragma unroll
                for (int j = 0; j < 2; j++)
                    STS128(Ab + col * 16384 + ao[j],
                           rA[col][j].x, rA[col][j].y, rA[col][j].z, rA[col][j].w);
#pragma unroll
            for (int j = 0; j < 4; j++)
                STS128(Bb + bo[j], h2u(f0[j][0], f0[j][1]), h2u(f0[j][2], f0[j][3]),
                                   h2u(f0[j][4], f0[j][5]), h2u(f0[j][6], f0[j][7]));
            {
                const size_t k1 = (size_t)(t * 128 + 64 + asub * 8);
                float f1[4][8];
#pragma unroll
                for (int j = 0; j < 4; j++)
#pragma unroll
                    for (int d = 0; d < 8; d++)
                        f1[j][d] = Bsrc[(k1 + d) * DIM + gcols[j]];
#pragma unroll
                for (int j = 0; j < 4; j++)
                    STS128(Bb + 32768 + bo[j], h2u(f1[j][0], f1[j][1]), h2u(f1[j][2], f1[j][3]),
                                               h2u(f1[j][4], f1[j][5]), h2u(f1[j][6], f1[j][7]));
            }
            FENCE_ASYNC();
            __syncwarp();
            if (lane == 0) MBAR_ARRIVE_LEADER(sb + s * 8);
        }
        { const int sf = (T - 1) & 1; MBAR_WAIT(sb + 32 + sf * 8, phD[sf]); }
    } else if (rank == 0) {
        if (elect_one()) {
            int phF[2] = {0, 0};
            for (int t = 0; t < T; t++) {
                const int s = t & 1;
                const uint32_t Ab = BUF + (uint32_t)s * STAGE_BYTES;
                const uint32_t Bb = Ab + 32768;
                MBAR_WAIT(sb + s * 8, phF[s]); phF[s] ^= 1;
                uint64_t dA = make_desc_sw128(Ab);
                uint64_t dB = make_desc_sw128(Bb);
#pragma unroll
                for (int c = 0; c < 8; c++) {
                    uint64_t ao2 = (uint64_t)((c >> 2) * 1024 + (c & 3) * 2);
                    uint64_t bo2 = (uint64_t)((c >> 2) * 2048 + (c & 3) * 2);
                    uint32_t en = (t > 0 || c > 0) ? 1u : 0u;
                    mma_f16_ss_cg2(tb,       dA + ao2, dB + bo2,        IDESC_F16_CG2, en);
                    mma_f16_ss_cg2(tb + 256, dA + ao2, dB + bo2 + 1024, IDESC_F16_CG2, en);
                }
                TC_COMMIT_MC_CG2(sb + 32 + s * 8, 0x3);
            }
        }
    }
    TC_FENCE_AFTER();

    // ---- epilogue: my 128 rows x 512 out cols (fp32) ----
    if (wid < 16) {
        const int rloc = (wid & 3) * 32 + lane;
        const int row  = m0 + rank * 128 + rloc;
        const bool ok  = row < cnt;
        int tok = 0;
        if (ok) tok = (g < NEXP) ? g_list[g * NT_TOK + row] : row;
        const int cq = wid >> 2;
        const size_t obase = (size_t)tok * DIM + n0 + cq * 128;
#pragma unroll
        for (int c = 0; c < 4; c++) {
            uint32_t dr[32];
            uint32_t col = (uint32_t)(cq * 128 + c * 32);
            TC_LD_X32(dr, tb + col);
            TC_WAIT_LD();
            if (ok) {
                if (accumulate) {
#pragma unroll
                    for (int q = 0; q < 8; q++) {
                        float4 o = *(float4*)&out[obase + c * 32 + q * 4];
                        o.x += __uint_as_float(dr[q*4]);   o.y += __uint_as_float(dr[q*4+1]);
                        o.z += __uint_as_float(dr[q*4+2]); o.w += __uint_as_float(dr[q*4+3]);
                        *(float4*)&out[obase + c * 32 + q * 4] = o;
                    }
                } else {
#pragma unroll
                    for (int q = 0; q < 8; q++)
                        *(float4*)&out[obase + c * 32 + q * 4] =
                            make_float4(__uint_as_float(dr[q*4]),   __uint_as_float(dr[q*4+1]),
                                        __uint_as_float(dr[q*4+2]), __uint_as_float(dr[q*4+3]));
                }
            }
        }
    }
    __syncthreads();
    if (tid == 0) {
#pragma unroll
        for (int s = 0; s < 2; s++) { MBAR_INVAL(sb + s * 8); MBAR_INVAL(sb + 32 + s * 8); }
    }
    __syncthreads();
    if (wid == 0) { TC_DEALLOC_CG2(tb, 512); }
    CLUSTER_SYNC();
#else
    // portable fallback
    for (int idx = threadIdx.x; idx < 128 * 512; idx += NTHREADS) {
        int r = idx >> 9, cc = idx & 511;
        int row = m0 + rank * 128 + r;
        if (row >= cnt) continue;
        const __half* arow = g_H + (size_t)(rowbase + row) * FDIM;
        int col = n0 + cc;
        float s = 0.f;
        for (int k = 0; k < FDIM; k++)
            s += __half2float(arow[k]) *
                 __half2float(__float2half_rn(Bsrc[(size_t)k * DIM + col]));
        int tok = (g < NEXP) ? g_list[g * NT_TOK + row] : row;
        size_t o = (size_t)tok * DIM + col;
        if (accumulate) out[o] += s; else out[o] = s;
    }
#endif
}

// ---------------- launch ----------------
extern "C" void kernel_launch(void* const* d_in, const int* in_sizes, int n_in,
                              void* d_out, int out_size)
{
    const float* x   = (const float*)d_in[0];
    const float* rw  = (const float*)d_in[1];
    const float* wgu = (const float*)d_in[2];
    const float* wdn = (const float*)d_in[3];
    const float* sgu = (const float*)d_in[4];
    const float* sdn = (const float*)d_in[5];
    float* out = (float*)d_out;

    cudaFuncSetAttribute(gemm1_tc, cudaFuncAttributeMaxDynamicSharedMemorySize, SMEM_BYTES);
    cudaFuncSetAttribute(gemm2_tc, cudaFuncAttributeMaxDynamicSharedMemorySize, SMEM_BYTES);

    router_kernel<<<NT_TOK / 8, 256>>>(x, rw);
    finalize_kernel<<<1, 1>>>();
    gather_kernel<<<2 * NT_TOK, 256>>>(x);
    gemm1_tc<<<dim3(2 * (NT_TOK / 256), FDIM / 256, 9), NTHREADS, SMEM_BYTES>>>(wgu, sgu);
    gemm2_tc<<<dim3(2 * (NT_TOK / 256), DIM / 512, NEXP), NTHREADS, SMEM_BYTES>>>(wdn, sdn, out, 0, 0);
    gemm2_tc<<<dim3(2 * (NT_TOK / 256), DIM / 512, 1), NTHREADS, SMEM_BYTES>>>(wdn, sdn, out, 8, 1);
}

// round 17
// speedup vs baseline: 1.7862x; 1.7862x over previous
#include <cuda_runtime.h>
#include <cuda_fp16.h>
#include <cstdint>

#define NT_TOK 4096
#define DIM    2048
#define FDIM   4096
#define TWOF   8192
#define NEXP   8

// ---------------- static device scratch ----------------
__device__ int    g_cnt[9];
__device__ int    g_cnt2[9];
__device__ int    g_off[9];
__device__ int    g_list[NEXP * NT_TOK];
__device__ float  g_gate[NEXP * NT_TOK];
__device__ __half g_X[2 * NT_TOK * (size_t)DIM];    // gathered gated input (fp16)
__device__ __half g_H[2 * NT_TOK * (size_t)FDIM];   // silu(g)*u (fp16)
// transposed fp16 weights, [n][k] row-major
__device__ __half g_Wgu[NEXP * (size_t)TWOF * DIM]; // 256 MB
__device__ __half g_Sgu[(size_t)TWOF * DIM];        // 32 MB
__device__ __half g_Wdn[NEXP * (size_t)DIM * FDIM]; // 128 MB
__device__ __half g_Sdn[(size_t)DIM * FDIM];        // 16 MB

// ---------------- helpers (arch-neutral) ----------------
__device__ __forceinline__ uint32_t h2u(float a, float b) {
    __half2 h = __floats2half2_rn(a, b);
    return *reinterpret_cast<uint32_t*>(&h);
}
__device__ __forceinline__ uint32_t smem_u32(const void* p) {
    uint32_t a;
    asm("{ .reg .u64 t; cvta.to.shared.u64 t, %1; cvt.u32.u64 %0, t; }" : "=r"(a) : "l"(p));
    return a;
}
#define SW128(o) ((o) ^ (((o) >> 3) & 0x70))

#if defined(__CUDA_ARCH__) && defined(__CUDA_ARCH_FEAT_SM103_ALL)
#define HAS_TCGEN05 1
#else
#define HAS_TCGEN05 0
#endif

#if HAS_TCGEN05
__device__ __forceinline__ uint32_t elect_one() {
    uint32_t p;
    asm volatile("{\n\t.reg .pred p;\n\telect.sync _|p, 0xFFFFFFFF;\n\t"
                 "selp.b32 %0, 1, 0, p;\n\t}" : "=r"(p));
    return p;
}
static __device__ __forceinline__ uint64_t make_desc_sw128(uint32_t addr) {
    const uint64_t base =
        (uint64_t(2) << 61) | (uint64_t(1) << 46) | (uint64_t(64) << 32) | (uint64_t(1) << 16);
    return base | ((uint64_t)(addr >> 4) & 0x3FFF);
}
// cg2 f16: dtype=F32(1)<<4 | atype=FP16(0) | btype=FP16(0) | (N/8)<<17 | (M/16)<<24
#define IDESC_F16_CG2 ((1u<<4)|((256u/8)<<17)|((256u/16)<<24))

__device__ __forceinline__ void mma_f16_ss_cg2(uint32_t d, uint64_t da, uint64_t db,
                                               uint32_t idesc, uint32_t en) {
    asm volatile(
        "{\n\t.reg .pred p;\n\tsetp.ne.u32 p, %4, 0;\n\t"
        "tcgen05.mma.cta_group::2.kind::f16 [%0], %1, %2, %3, "
        "{%5, %5, %5, %5, %5, %5, %5, %5}, p;\n\t}"
        :: "r"(d), "l"(da), "l"(db), "r"(idesc), "r"(en), "r"(0u) : "memory");
}

#define TC_ALLOC_CG2(sm, n)   asm volatile("tcgen05.alloc.cta_group::2.sync.aligned.shared::cta.b32 [%0], %1;" :: "r"(sm), "r"(n) : "memory")
#define TC_DEALLOC_CG2(tb, n) asm volatile("tcgen05.dealloc.cta_group::2.sync.aligned.b32 %0, %1;" :: "r"(tb), "r"(n))
#define TC_RELINQ_CG2()       asm volatile("tcgen05.relinquish_alloc_permit.cta_group::2.sync.aligned;")
#define TC_COMMIT_MC_CG2(mb, mask) \
    asm volatile("tcgen05.commit.cta_group::2.mbarrier::arrive::one.shared::cluster.multicast::cluster.b64 [%0], %1;" \
                 :: "r"(mb), "h"((uint16_t)(mask)) : "memory")
#define TC_FENCE_AFTER()  asm volatile("tcgen05.fence::after_thread_sync;" ::: "memory")
#define TC_WAIT_LD()      asm volatile("tcgen05.wait::ld.sync.aligned;" ::: "memory")
#define FENCE_ASYNC()     asm volatile("fence.proxy.async.shared::cta;" ::: "memory")
#define MBAR_INIT(mb, c)  asm volatile("mbarrier.init.shared.b64 [%0], %1;" :: "r"(mb), "r"(c) : "memory")
#define MBAR_INVAL(mb)    asm volatile("mbarrier.inval.shared.b64 [%0];" :: "r"(mb) : "memory")
#define MBAR_ARRIVE_LEADER(mb)                                                       \
    asm volatile("{\n\t.reg .b32 la;\n\tand.b32 la, %0, 0xFEFFFFFF;\n\t"             \
                 "mbarrier.arrive.shared::cluster.b64 _, [la];\n\t}"                 \
                 :: "r"(mb) : "memory")
#define CLUSTER_SYNC() do {                                                          \
    asm volatile("barrier.cluster.arrive.aligned;" ::: "memory");                    \
    asm volatile("barrier.cluster.wait.aligned;" ::: "memory");                      \
} while (0)

#define MBAR_WAIT(mb, ph) do {                                                       \
    uint32_t _m = (mb); uint32_t _p = (ph); uint32_t _d;                             \
    asm volatile("{\n\t.reg .pred p;\n\t"                                            \
        "mbarrier.try_wait.parity.acquire.cta.shared::cta.b64 p, [%1], %2;\n\t"      \
        "selp.b32 %0, 1, 0, p;\n\t}" : "=r"(_d) : "r"(_m), "r"(_p) : "memory");      \
    if (!_d) {                                                                       \
        asm volatile("{\n\t.reg .pred P1;\n\tWL_%=:\n\t"                             \
            "mbarrier.try_wait.parity.acquire.cta.shared::cta.b64 P1, [%0], %1, 0x989680;\n\t" \
            "@P1 bra.uni WD_%=;\n\tbra.uni WL_%=;\n\tWD_%=:\n\t}"                    \
            :: "r"(_m), "r"(_p) : "memory");                                         \
    }                                                                                \
} while (0)

#define TC_LD_X32(r, addr)                                                           \
    asm volatile("tcgen05.ld.sync.aligned.32x32b.x32.b32 "                           \
        "{%0,%1,%2,%3,%4,%5,%6,%7,%8,%9,%10,%11,%12,%13,%14,%15,"                    \
        "%16,%17,%18,%19,%20,%21,%22,%23,%24,%25,%26,%27,%28,%29,%30,%31}, [%32];"   \
        : "=r"((r)[0]),"=r"((r)[1]),"=r"((r)[2]),"=r"((r)[3]),                       \
          "=r"((r)[4]),"=r"((r)[5]),"=r"((r)[6]),"=r"((r)[7]),                       \
          "=r"((r)[8]),"=r"((r)[9]),"=r"((r)[10]),"=r"((r)[11]),                     \
          "=r"((r)[12]),"=r"((r)[13]),"=r"((r)[14]),"=r"((r)[15]),                   \
          "=r"((r)[16]),"=r"((r)[17]),"=r"((r)[18]),"=r"((r)[19]),                   \
          "=r"((r)[20]),"=r"((r)[21]),"=r"((r)[22]),"=r"((r)[23]),                   \
          "=r"((r)[24]),"=r"((r)[25]),"=r"((r)[26]),"=r"((r)[27]),                   \
          "=r"((r)[28]),"=r"((r)[29]),"=r"((r)[30]),"=r"((r)[31])                    \
        : "r"(addr))

#define STS128(addr, a, b, c, d)                                                     \
    asm volatile("st.shared.v4.b32 [%0], {%1, %2, %3, %4};"                          \
                 :: "r"(addr), "r"(a), "r"(b), "r"(c), "r"(d) : "memory")
#endif  // HAS_TCGEN05

// K_tile=128 halves. stage = A(32KB: 2 katom 16KB) + B(64KB: 2 katom 32KB)
#define STAGE_BYTES 98304
#define NSTAGE 2
#define SMEM_BYTES (2048 + NSTAGE * STAGE_BYTES)
#define NTHREADS 544
#define FULL_ARRIVALS 32

// ---------------- router ----------------
__global__ __launch_bounds__(256) void router_kernel(
    const float* __restrict__ x, const float* __restrict__ rw)
{
    int t = blockIdx.x * 8 + (threadIdx.x >> 5);
    int lane = threadIdx.x & 31;
    const float* xr = x + (size_t)t * DIM;
    float p[8];
#pragma unroll
    for (int e = 0; e < 8; e++) p[e] = 0.f;
    for (int k = lane; k < DIM; k += 32) {
        float xv = xr[k];
#pragma unroll
        for (int e = 0; e < 8; e++) p[e] += xv * rw[e * DIM + k];
    }
#pragma unroll
    for (int e = 0; e < 8; e++)
#pragma unroll
        for (int o = 16; o > 0; o >>= 1) p[e] += __shfl_xor_sync(~0u, p[e], o);
    if (lane == 0) {
        float best = p[0]; int bi = 0;
#pragma unroll
        for (int e = 1; e < 8; e++) if (p[e] > best) { best = p[e]; bi = e; }
        float gate = 1.0f / (1.0f + expf(-best));
        int pos = atomicAdd(&g_cnt[bi], 1);
        g_list[bi * NT_TOK + pos] = t;
        g_gate[bi * NT_TOK + pos] = gate;
    }
}

__global__ void finalize_kernel() {
    int o = 0;
    for (int e = 0; e < 8; e++) { g_off[e] = o; g_cnt2[e] = g_cnt[e]; o += g_cnt[e]; }
    g_off[8] = NT_TOK; g_cnt2[8] = NT_TOK;
}

// ---------------- gather: g_X[slot] = fp16(gate * x[tok]); re-zero g_cnt ----
__global__ __launch_bounds__(256) void gather_kernel(const float* __restrict__ x)
{
    int row = blockIdx.x;
    int tok; float gate;
    if (row < NT_TOK) {
        int e = 0;
#pragma unroll
        for (int i = 1; i < 8; i++) if (row >= g_off[i]) e = i;
        int idx = row - g_off[e];
        tok  = g_list[e * NT_TOK + idx];
        gate = g_gate[e * NT_TOK + idx];
    } else { tok = row - NT_TOK; gate = 1.f; }
    const float4* src = (const float4*)(x + (size_t)tok * DIM);
    __half2* dst = (__half2*)(g_X + (size_t)row * DIM);
    for (int j = threadIdx.x; j < DIM / 4; j += 256) {
        float4 v = src[j];
        dst[j * 2]     = __floats2half2_rn(v.x * gate, v.y * gate);
        dst[j * 2 + 1] = __floats2half2_rn(v.z * gate, v.w * gate);
    }
    if (blockIdx.x == 0 && threadIdx.x < 9) g_cnt[threadIdx.x] = 0;
}

// ---------------- weight transpose+convert: src[k][n] f32 -> dst[n][k] fp16 ----
// grid: (N/64, K/64, nmat), block 256
__global__ __launch_bounds__(256) void transpose_kernel(
    const float* __restrict__ src, __half* __restrict__ dst, int K, int N)
{
    const float* s = src + (size_t)blockIdx.z * K * N;
    __half* d = dst + (size_t)blockIdx.z * K * N;
    const int n0 = blockIdx.x * 64, k0 = blockIdx.y * 64;
    __shared__ float tile[64][65];
    const int t = threadIdx.x;
#pragma unroll
    for (int i = 0; i < 4; i++) {
        int idx = t + 256 * i;
        int r = idx >> 4, c = (idx & 15) * 4;
        float4 v = *(const float4*)(s + (size_t)(k0 + r) * N + n0 + c);
        tile[r][c] = v.x; tile[r][c + 1] = v.y; tile[r][c + 2] = v.z; tile[r][c + 3] = v.w;
    }
    __syncthreads();
#pragma unroll
    for (int i = 0; i < 2; i++) {
        int idx = t + 256 * i;
        int nr = idx >> 3, kc = (idx & 7) * 8;
        uint32_t h[4];
#pragma unroll
        for (int q = 0; q < 4; q++)
            h[q] = h2u(tile[kc + 2 * q][nr], tile[kc + 2 * q + 1][nr]);
        *(uint4*)(d + (size_t)(n0 + nr) * K + k0 + kc) = make_uint4(h[0], h[1], h[2], h[3]);
    }
}

// ================= GEMM1 (cg2 pair tile M=256 x N=512, fp16, K_tile=128) =====
// grid: (2*NT_TOK/256, FDIM/256, 9). cluster (2,1,1), block 544.
__global__ __launch_bounds__(NTHREADS, 1) __cluster_dims__(2, 1, 1)
void gemm1_tc()
{
    const int g   = blockIdx.z;
    const int cnt = (g < NEXP) ? g_cnt2[g] : NT_TOK;
    const int m0  = (blockIdx.x >> 1) * 256;
    if (m0 >= cnt) return;
    const int rank = blockIdx.x & 1;
    const int hb  = blockIdx.y;
    const __half* Bt = (g < NEXP) ? (g_Wgu + (size_t)g * TWOF * DIM) : g_Sgu;
    const int rowbase = (g < NEXP) ? g_off[g] : NT_TOK;

#if HAS_TCGEN05
    extern __shared__ char smraw[];
    uint32_t sb = (smem_u32(smraw) + 1023u) & ~1023u;
    const uint32_t TP  = sb + 64;
    const uint32_t BUF = sb + 1024;

    const int tid = threadIdx.x, wid = tid >> 5, lane = tid & 31;

    if (wid == 0) { TC_ALLOC_CG2(TP, 512); TC_RELINQ_CG2(); }
    if (tid == 0) {
#pragma unroll
        for (int s = 0; s < 2; s++) { MBAR_INIT(sb + s * 8, FULL_ARRIVALS); MBAR_INIT(sb + 32 + s * 8, 1); }
    }
    __syncthreads();
    CLUSTER_SYNC();
    uint32_t tb;
    asm volatile("ld.shared.b32 %0, [%1];" : "=r"(tb) : "r"(TP));

    const int T = DIM / 128;

    if (tid < 512) {
        const int asub = tid & 7;
        const int ar0  = tid >> 3;        // 0..63
        const __half* abase = g_X + (size_t)(rowbase + m0 + rank * 128) * DIM;
        uint32_t ao[2];
#pragma unroll
        for (int j = 0; j < 2; j++)
            ao[j] = SW128((uint32_t)((ar0 + 64 * j) * 128 + asub * 16));

        // B rows: nr = tid>>3 + 64j ; global col per atom/rank
        const __half* bsrcs[4]; uint32_t bo[4];
#pragma unroll
        for (int j = 0; j < 4; j++) {
            int nr = (tid >> 3) + 64 * j;
            int atom = nr >> 7, within = nr & 127;
            int gcol = (atom == 0) ? (hb * 256 + rank * 128 + within)
                                   : (FDIM + hb * 256 + rank * 128 + within);
            bsrcs[j] = Bt + (size_t)gcol * DIM;
            bo[j] = SW128((uint32_t)(nr * 128 + asub * 16));
        }

        int phD[2] = {0, 0};
        for (int t = 0; t < T; t++) {
            const int s = t & 1;
            const uint32_t Ab = BUF + (uint32_t)s * STAGE_BYTES;
            const uint32_t Bb = Ab + 32768;
            uint4 rA[2][2], rB[4][2];
#pragma unroll
            for (int c = 0; c < 2; c++)
#pragma unroll
                for (int j = 0; j < 2; j++)
                    rA[c][j] = *(const uint4*)(abase + (size_t)(ar0 + 64 * j) * DIM
                                               + t * 128 + c * 64 + asub * 8);
#pragma unroll
            for (int j = 0; j < 4; j++)
#pragma unroll
                for (int c = 0; c < 2; c++)
                    rB[j][c] = *(const uint4*)(bsrcs[j] + t * 128 + c * 64 + asub * 8);
            if (t >= 2) { MBAR_WAIT(sb + 32 + s * 8, phD[s]); phD[s] ^= 1; }
#pragma unroll
            for (int c = 0; c < 2; c++)
#pragma unroll
                for (int j = 0; j < 2; j++)
                    STS128(Ab + c * 16384 + ao[j],
                           rA[c][j].x, rA[c][j].y, rA[c][j].z, rA[c][j].w);
#pragma unroll
            for (int c = 0; c < 2; c++)
#pragma unroll
                for (int j = 0; j < 4; j++)
                    STS128(Bb + c * 32768 + bo[j],
                           rB[j][c].x, rB[j][c].y, rB[j][c].z, rB[j][c].w);
            FENCE_ASYNC();
            __syncwarp();
            if (lane == 0) MBAR_ARRIVE_LEADER(sb + s * 8);
        }
        { const int sf = (T - 1) & 1; MBAR_WAIT(sb + 32 + sf * 8, phD[sf]); }
    } else if (rank == 0) {
        if (elect_one()) {
            int phF[2] = {0, 0};
            for (int t = 0; t < T; t++) {
                const int s = t & 1;
                const uint32_t Ab = BUF + (uint32_t)s * STAGE_BYTES;
                const uint32_t Bb = Ab + 32768;
                MBAR_WAIT(sb + s * 8, phF[s]); phF[s] ^= 1;
                uint64_t dA = make_desc_sw128(Ab);
                uint64_t dB = make_desc_sw128(Bb);
#pragma unroll
                for (int c = 0; c < 8; c++) {   // 8 K16 chunks: katom=c>>2, sub=c&3
                    uint64_t ao2 = (uint64_t)((c >> 2) * 1024 + (c & 3) * 2);
                    uint64_t bo2 = (uint64_t)((c >> 2) * 2048 + (c & 3) * 2);
                    uint32_t en = (t > 0 || c > 0) ? 1u : 0u;
                    mma_f16_ss_cg2(tb,       dA + ao2, dB + bo2,        IDESC_F16_CG2, en);
                    mma_f16_ss_cg2(tb + 256, dA + ao2, dB + bo2 + 1024, IDESC_F16_CG2, en);
                }
                TC_COMMIT_MC_CG2(sb + 32 + s * 8, 0x3);
            }
        }
    }
    TC_FENCE_AFTER();

    // ---- epilogue: my 128 rows x 512 cols (gate atom0 | up atom1) -> g_H (fp16) ----
    if (wid < 16) {
        const int rloc = (wid & 3) * 32 + lane;
        const int row  = m0 + rank * 128 + rloc;
        const bool ok  = row < cnt;
        const int cq   = wid >> 2;
        const size_t hbase = (size_t)(rowbase + row) * FDIM + hb * 256 + cq * 64;
#pragma unroll
        for (int c = 0; c < 2; c++) {
            uint32_t gr[32], ur[32];
            uint32_t col = (uint32_t)(cq * 64 + c * 32);
            TC_LD_X32(gr, tb + col);
            TC_LD_X32(ur, tb + 256 + col);
            TC_WAIT_LD();
            if (ok) {
                uint32_t hp[16];
#pragma unroll
                for (int r = 0; r < 16; r++) {
                    float gv0 = __uint_as_float(gr[2*r]),   uv0 = __uint_as_float(ur[2*r]);
                    float gv1 = __uint_as_float(gr[2*r+1]), uv1 = __uint_as_float(ur[2*r+1]);
                    hp[r] = h2u(gv0 / (1.f + expf(-gv0)) * uv0,
                                gv1 / (1.f + expf(-gv1)) * uv1);
                }
#pragma unroll
                for (int q = 0; q < 4; q++)
                    *(uint4*)&g_H[hbase + c * 32 + q * 8] =
                        make_uint4(hp[q*4], hp[q*4+1], hp[q*4+2], hp[q*4+3]);
            }
        }
    }
    __syncthreads();
    if (tid == 0) {
#pragma unroll
        for (int s = 0; s < 2; s++) { MBAR_INVAL(sb + s * 8); MBAR_INVAL(sb + 32 + s * 8); }
    }
    __syncthreads();
    if (wid == 0) { TC_DEALLOC_CG2(tb, 512); }
    CLUSTER_SYNC();
#else
    // portable fallback
    for (int idx = threadIdx.x; idx < 128 * 256; idx += NTHREADS) {
        int r = idx >> 8, cc = idx & 255;
        int row = m0 + rank * 128 + r;
        if (row >= cnt) continue;
        const __half* arow = g_X + (size_t)(rowbase + row) * DIM;
        int col = hb * 256 + cc;
        float sg = 0.f, su = 0.f;
        for (int k = 0; k < DIM; k++) {
            float a = __half2float(arow[k]);
            sg += a * __half2float(Bt[(size_t)col * DIM + k]);
            su += a * __half2float(Bt[(size_t)(FDIM + col) * DIM + k]);
        }
        g_H[(size_t)(rowbase + row) * FDIM + col] =
            __float2half_rn(sg / (1.f + expf(-sg)) * su);
    }
#endif
}

// ================= GEMM2 (cg2 pair tile M=256 x N=512, fp16, K_tile=128) =====
// grid: (2*NT_TOK/256, DIM/512, nz). cluster (2,1,1), block 544.
__global__ __launch_bounds__(NTHREADS, 1) __cluster_dims__(2, 1, 1)
void gemm2_tc(float* __restrict__ out, int gstart, int accumulate)
{
    const int g   = gstart + blockIdx.z;
    const int cnt = (g < NEXP) ? g_cnt2[g] : NT_TOK;
    const int m0  = (blockIdx.x >> 1) * 256;
    if (m0 >= cnt) return;
    const int rank = blockIdx.x & 1;
    const int n0  = blockIdx.y * 512;
    const __half* Bt = (g < NEXP) ? (g_Wdn + (size_t)g * DIM * FDIM) : g_Sdn;
    const int rowbase = (g < NEXP) ? g_off[g] : NT_TOK;

#if HAS_TCGEN05
    extern __shared__ char smraw[];
    uint32_t sb = (smem_u32(smraw) + 1023u) & ~1023u;
    const uint32_t TP  = sb + 64;
    const uint32_t BUF = sb + 1024;

    const int tid = threadIdx.x, wid = tid >> 5, lane = tid & 31;

    if (wid == 0) { TC_ALLOC_CG2(TP, 512); TC_RELINQ_CG2(); }
    if (tid == 0) {
#pragma unroll
        for (int s = 0; s < 2; s++) { MBAR_INIT(sb + s * 8, FULL_ARRIVALS); MBAR_INIT(sb + 32 + s * 8, 1); }
    }
    __syncthreads();
    CLUSTER_SYNC();
    uint32_t tb;
    asm volatile("ld.shared.b32 %0, [%1];" : "=r"(tb) : "r"(TP));

    const int T = FDIM / 128;

    if (tid < 512) {
        const int asub = tid & 7;
        const int ar0  = tid >> 3;
        const __half* abase = g_H + (size_t)(rowbase + m0 + rank * 128) * FDIM;
        uint32_t ao[2];
#pragma unroll
        for (int j = 0; j < 2; j++)
            ao[j] = SW128((uint32_t)((ar0 + 64 * j) * 128 + asub * 16));

        const __half* bsrcs[4]; uint32_t bo[4];
#pragma unroll
        for (int j = 0; j < 4; j++) {
            int nr = (tid >> 3) + 64 * j;
            int atom = nr >> 7, within = nr & 127;
            int gcol = n0 + atom * 256 + rank * 128 + within;
            bsrcs[j] = Bt + (size_t)gcol * FDIM;
            bo[j] = SW128((uint32_t)(nr * 128 + asub * 16));
        }

        int phD[2] = {0, 0};
        for (int t = 0; t < T; t++) {
            const int s = t & 1;
            const uint32_t Ab = BUF + (uint32_t)s * STAGE_BYTES;
            const uint32_t Bb = Ab + 32768;
            uint4 rA[2][2], rB[4][2];
#pragma unroll
            for (int c = 0; c < 2; c++)
#pragma unroll
                for (int j = 0; j < 2; j++)
                    rA[c][j] = *(const uint4*)(abase + (size_t)(ar0 + 64 * j) * FDIM
                                               + t * 128 + c * 64 + asub * 8);
#pragma unroll
            for (int j = 0; j < 4; j++)
#pragma unroll
                for (int c = 0; c < 2; c++)
                    rB[j][c] = *(const uint4*)(bsrcs[j] + t * 128 + c * 64 + asub * 8);
            if (t >= 2) { MBAR_WAIT(sb + 32 + s * 8, phD[s]); phD[s] ^= 1; }
#pragma unroll
            for (int c = 0; c < 2; c++)
#pragma unroll
                for (int j = 0; j < 2; j++)
                    STS128(Ab + c * 16384 + ao[j],
                           rA[c][j].x, rA[c][j].y, rA[c][j].z, rA[c][j].w);
#pragma unroll
            for (int c = 0; c < 2; c++)
#pragma unroll
                for (int j = 0; j < 4; j++)
                    STS128(Bb + c * 32768 + bo[j],
                           rB[j][c].x, rB[j][c].y, rB[j][c].z, rB[j][c].w);
            FENCE_ASYNC();
            __syncwarp();
            if (lane == 0) MBAR_ARRIVE_LEADER(sb + s * 8);
        }
        { const int sf = (T - 1) & 1; MBAR_WAIT(sb + 32 + sf * 8, phD[sf]); }
    } else if (rank == 0) {
        if (elect_one()) {
            int phF[2] = {0, 0};
            for (int t = 0; t < T; t++) {
                const int s = t & 1;
                const uint32_t Ab = BUF + (uint32_t)s * STAGE_BYTES;
                const uint32_t Bb = Ab + 32768;
                MBAR_WAIT(sb + s * 8, phF[s]); phF[s] ^= 1;
                uint64_t dA = make_desc_sw128(Ab);
                uint64_t dB = make_desc_sw128(Bb);
#pragma unroll
                for (int c = 0; c < 8; c++) {
                    uint64_t ao2 = (uint64_t)((c >> 2) * 1024 + (c & 3) * 2);
                    uint64_t bo2 = (uint64_t)((c >> 2) * 2048 + (c & 3) * 2);
                    uint32_t en = (t > 0 || c > 0) ? 1u : 0u;
                    mma_f16_ss_cg2(tb,       dA + ao2, dB + bo2,        IDESC_F16_CG2, en);
                    mma_f16_ss_cg2(tb + 256, dA + ao2, dB + bo2 + 1024, IDESC_F16_CG2, en);
                }
                TC_COMMIT_MC_CG2(sb + 32 + s * 8, 0x3);
            }
        }
    }
    TC_FENCE_AFTER();

    // ---- epilogue: my 128 rows x 512 out cols (fp32) ----
    if (wid < 16) {
        const int rloc = (wid & 3) * 32 + lane;
        const int row  = m0 + rank * 128 + rloc;
        const bool ok  = row < cnt;
        int tok = 0;
        if (ok) tok = (g < NEXP) ? g_list[g * NT_TOK + row] : row;
        const int cq = wid >> 2;
        const size_t obase = (size_t)tok * DIM + n0 + cq * 128;
#pragma unroll
        for (int c = 0; c < 4; c++) {
            uint32_t dr[32];
            uint32_t col = (uint32_t)(cq * 128 + c * 32);
            TC_LD_X32(dr, tb + col);
            TC_WAIT_LD();
            if (ok) {
                if (accumulate) {
#pragma unroll
                    for (int q = 0; q < 8; q++) {
                        float4 o = *(float4*)&out[obase + c * 32 + q * 4];
                        o.x += __uint_as_float(dr[q*4]);   o.y += __uint_as_float(dr[q*4+1]);
                        o.z += __uint_as_float(dr[q*4+2]); o.w += __uint_as_float(dr[q*4+3]);
                        *(float4*)&out[obase + c * 32 + q * 4] = o;
                    }
                } else {
#pragma unroll
                    for (int q = 0; q < 8; q++)
                        *(float4*)&out[obase + c * 32 + q * 4] =
                            make_float4(__uint_as_float(dr[q*4]),   __uint_as_float(dr[q*4+1]),
                                        __uint_as_float(dr[q*4+2]), __uint_as_float(dr[q*4+3]));
                }
            }
        }
    }
    __syncthreads();
    if (tid == 0) {
#pragma unroll
        for (int s = 0; s < 2; s++) { MBAR_INVAL(sb + s * 8); MBAR_INVAL(sb + 32 + s * 8); }
    }
    __syncthreads();
    if (wid == 0) { TC_DEALLOC_CG2(tb, 512); }
    CLUSTER_SYNC();
#else
    // portable fallback
    for (int idx = threadIdx.x; idx < 128 * 512; idx += NTHREADS) {
        int r = idx >> 9, cc = idx & 511;
        int row = m0 + rank * 128 + r;
        if (row >= cnt) continue;
        const __half* arow = g_H + (size_t)(rowbase + row) * FDIM;
        int col = n0 + cc;
        float s = 0.f;
        for (int k = 0; k < FDIM; k++)
            s += __half2float(arow[k]) * __half2float(Bt[(size_t)col * FDIM + k]);
        int tok = (g < NEXP) ? g_list[g * NT_TOK + row] : row;
        size_t o = (size_t)tok * DIM + col;
        if (accumulate) out[o] += s; else out[o] = s;
    }
#endif
}

// ---------------- launch ----------------
extern "C" void kernel_launch(void* const* d_in, const int* in_sizes, int n_in,
                              void* d_out, int out_size)
{
    const float* x   = (const float*)d_in[0];
    const float* rw  = (const float*)d_in[1];
    const float* wgu = (const float*)d_in[2];
    const float* wdn = (const float*)d_in[3];
    const float* sgu = (const float*)d_in[4];
    const float* sdn = (const float*)d_in[5];
    float* out = (float*)d_out;

    cudaFuncSetAttribute(gemm1_tc, cudaFuncAttributeMaxDynamicSharedMemorySize, SMEM_BYTES);
    cudaFuncSetAttribute(gemm2_tc, cudaFuncAttributeMaxDynamicSharedMemorySize, SMEM_BYTES);

    __half *d_wgu, *d_sgu, *d_wdn, *d_sdn;
    cudaGetSymbolAddress((void**)&d_wgu, g_Wgu);
    cudaGetSymbolAddress((void**)&d_sgu, g_Sgu);
    cudaGetSymbolAddress((void**)&d_wdn, g_Wdn);
    cudaGetSymbolAddress((void**)&d_sdn, g_Sdn);

    // weight transpose+convert (fp32 [k][n] -> fp16 [n][k])
    transpose_kernel<<<dim3(TWOF / 64, DIM / 64, NEXP), 256>>>(wgu, d_wgu, DIM, TWOF);
    transpose_kernel<<<dim3(TWOF / 64, DIM / 64, 1),    256>>>(sgu, d_sgu, DIM, TWOF);
    transpose_kernel<<<dim3(DIM / 64, FDIM / 64, NEXP), 256>>>(wdn, d_wdn, FDIM, DIM);
    transpose_kernel<<<dim3(DIM / 64, FDIM / 64, 1),    256>>>(sdn, d_sdn, FDIM, DIM);

    router_kernel<<<NT_TOK / 8, 256>>>(x, rw);
    finalize_kernel<<<1, 1>>>();
    gather_kernel<<<2 * NT_TOK, 256>>>(x);
    gemm1_tc<<<dim3(2 * (NT_TOK / 256), FDIM / 256, 9), NTHREADS, SMEM_BYTES>>>();
    gemm2_tc<<<dim3(2 * (NT_TOK / 256), DIM / 512, NEXP), NTHREADS, SMEM_BYTES>>>(out, 0, 0);
    gemm2_tc<<<dim3(2 * (NT_TOK / 256), DIM / 512, 1), NTHREADS, SMEM_BYTES>>>(out, 8, 1);
}